// round 8
// baseline (speedup 1.0000x reference)
#include <cuda_runtime.h>

#define HIDDEN   64
#define GROUP    256        // threads per batch element: (unit j, k-quarter)
#define NTHREADS 512        // 2 batch groups per CTA, 16 warps
#define QSTRIDE  20         // padded quarter stride (floats) -> conflict-free LDS

// ---------- packed f32x2 helpers ----------
__device__ __forceinline__ unsigned long long ffma2(unsigned long long a,
                                                    unsigned long long b,
                                                    unsigned long long c) {
    unsigned long long d;
    asm("fma.rn.f32x2 %0, %1, %2, %3;" : "=l"(d) : "l"(a), "l"(b), "l"(c));
    return d;
}
__device__ __forceinline__ unsigned long long fadd2(unsigned long long a,
                                                    unsigned long long b) {
    unsigned long long d;
    asm("add.rn.f32x2 %0, %1, %2;" : "=l"(d) : "l"(a), "l"(b));
    return d;
}
__device__ __forceinline__ unsigned long long pack2(float lo, float hi) {
    unsigned long long r;
    asm("mov.b64 %0, {%1, %2};" : "=l"(r) : "f"(lo), "f"(hi));
    return r;
}
__device__ __forceinline__ float2 unpack2(unsigned long long v) {
    float2 r;
    asm("mov.b64 {%0, %1}, %2;" : "=f"(r.x), "=f"(r.y) : "l"(v));
    return r;
}
__device__ __forceinline__ float tanh_approx(float x) {   // 1 MUFU
    float r; asm("tanh.approx.f32 %0, %1;" : "=f"(r) : "f"(x)); return r;
}

// one named barrier per batch group per step
__device__ __forceinline__ void bar_group(int id) {
    asm volatile("bar.sync %0, %1;" :: "r"(id), "r"(GROUP) : "memory");
}

__global__ void __launch_bounds__(NTHREADS, 1)
gru_scan_kernel(const float* __restrict__ x,
                const float* __restrict__ W_ih,
                const float* __restrict__ W_hh,
                const float* __restrict__ b_ih,
                const float* __restrict__ b_hh,
                const float* __restrict__ W_fc,
                const float* __restrict__ b_fc,
                float* __restrict__ out,
                int Btotal, int T)
{
    // h stored padded: unit k lives at (k>>4)*QSTRIDE + (k&15)
    __shared__ __align__(16) float h_sh[2][2][4 * QSTRIDE];  // [parity][group][padded]
    __shared__ float red_sh[2][8];

    const int tid  = threadIdx.x;
    const int m    = tid / GROUP;          // batch slot (warps 0-7 | 8-15)
    const int u    = tid % GROUP;
    const int wg   = u / 32;               // warp within group 0..7
    const int lane = u % 32;
    const int q    = lane >> 3;            // k-quarter 0..3
    const int j    = wg * 8 + (lane & 7);  // hidden unit
    const int b    = blockIdx.x * 2 + m;

    // ---- 3 gate quarter-rows in registers: 3 x 8 packed f32x2 (48 regs) ----
    unsigned long long wreg[3][8];
    #pragma unroll
    for (int g = 0; g < 3; g++) {
        const float4* row = reinterpret_cast<const float4*>(
            W_hh + (g * HIDDEN + j) * HIDDEN + q * 16);
        #pragma unroll
        for (int i = 0; i < 4; i++) {
            float4 v = row[i];
            wreg[g][2 * i]     = pack2(v.x, v.y);
            wreg[g][2 * i + 1] = pack2(v.z, v.w);
        }
    }

    // per-unit constants (pre-halved for the tanh-sigmoid identity)
    const float wr_h = 0.5f * W_ih[j];
    const float br_h = 0.5f * (b_ih[j] + b_hh[j]);
    const float wz_h = 0.5f * W_ih[HIDDEN + j];
    const float bz_h = 0.5f * (b_ih[HIDDEN + j] + b_hh[HIDDEN + j]);
    const float wn   = W_ih[2 * HIDDEN + j];
    const float bihn = b_ih[2 * HIDDEN + j];
    const float bhhn = b_hh[2 * HIDDEN + j];
    const float wfc  = W_fc[j];
    const float bfc  = __ldg(b_fc);

    const float* xb = x + (size_t)((b < Btotal) ? b : 0) * T;
    float xv    = __ldg(xb);
    float h_old = 0.0f;
    const int joff = ((j >> 4) * QSTRIDE) + (j & 15);   // my unit's padded slot

    if (q == 0) h_sh[0][m][joff] = 0.0f;
    __syncthreads();

    const int barid = 1 + m;

    for (int t = 0; t < T; t++) {
        const int par = t & 1, nxt = par ^ 1;
        // my k-quarter of h: 16 floats at padded offset q*QSTRIDE (16B aligned)
        const ulonglong2* h2 = reinterpret_cast<const ulonglong2*>(
            h_sh[par][m] + q * QSTRIDE);

        int tn = (t + 1 < T) ? t + 1 : T - 1;
        float xnext = __ldg(xb + tn);
        float arh = fmaf(xv, wr_h, br_h);
        float azh = fmaf(xv, wz_h, bz_h);
        float ain = fmaf(xv, wn, bihn);

        // ---- load quarter of h once (4 LDS.128), reuse for 3 gates ----
        unsigned long long hv[8];
        #pragma unroll
        for (int i = 0; i < 4; i++) {
            ulonglong2 v = h2[i];
            hv[2 * i]     = v.x;
            hv[2 * i + 1] = v.y;
        }

        // ======== r gate first (start its MUFU early) ========
        float dr;
        {
            unsigned long long q0 = ffma2(wreg[0][0], hv[0], 0ull);
            unsigned long long q1 = ffma2(wreg[0][1], hv[1], 0ull);
            unsigned long long q2 = ffma2(wreg[0][2], hv[2], 0ull);
            unsigned long long q3 = ffma2(wreg[0][3], hv[3], 0ull);
            q0 = ffma2(wreg[0][4], hv[4], q0);
            q1 = ffma2(wreg[0][5], hv[5], q1);
            q2 = ffma2(wreg[0][6], hv[6], q2);
            q3 = ffma2(wreg[0][7], hv[7], q3);
            float2 sp = unpack2(fadd2(fadd2(q0, q1), fadd2(q2, q3)));
            dr = sp.x + sp.y;
        }
        dr += __shfl_xor_sync(0xffffffffu, dr, 8);
        dr += __shfl_xor_sync(0xffffffffu, dr, 16);
        float taur = tanh_approx(fmaf(0.5f, dr, arh));   // overlaps z/n dots

        // ======== z gate ========
        float dz;
        {
            unsigned long long q0 = ffma2(wreg[1][0], hv[0], 0ull);
            unsigned long long q1 = ffma2(wreg[1][1], hv[1], 0ull);
            unsigned long long q2 = ffma2(wreg[1][2], hv[2], 0ull);
            unsigned long long q3 = ffma2(wreg[1][3], hv[3], 0ull);
            q0 = ffma2(wreg[1][4], hv[4], q0);
            q1 = ffma2(wreg[1][5], hv[5], q1);
            q2 = ffma2(wreg[1][6], hv[6], q2);
            q3 = ffma2(wreg[1][7], hv[7], q3);
            float2 sp = unpack2(fadd2(fadd2(q0, q1), fadd2(q2, q3)));
            dz = sp.x + sp.y;
        }
        dz += __shfl_xor_sync(0xffffffffu, dz, 8);
        dz += __shfl_xor_sync(0xffffffffu, dz, 16);
        float tauz = tanh_approx(fmaf(0.5f, dz, azh));

        // ======== n gate ========
        float dn;
        {
            unsigned long long q0 = ffma2(wreg[2][0], hv[0], 0ull);
            unsigned long long q1 = ffma2(wreg[2][1], hv[1], 0ull);
            unsigned long long q2 = ffma2(wreg[2][2], hv[2], 0ull);
            unsigned long long q3 = ffma2(wreg[2][3], hv[3], 0ull);
            q0 = ffma2(wreg[2][4], hv[4], q0);
            q1 = ffma2(wreg[2][5], hv[5], q1);
            q2 = ffma2(wreg[2][6], hv[6], q2);
            q3 = ffma2(wreg[2][7], hv[7], q3);
            float2 sp = unpack2(fadd2(fadd2(q0, q1), fadd2(q2, q3)));
            dn = sp.x + sp.y;
        }
        dn += __shfl_xor_sync(0xffffffffu, dn, 8);
        dn += __shfl_xor_sync(0xffffffffu, dn, 16);

        // ======== nonlinearity + update (all quarter-threads, redundant) ========
        float dnb  = dn + bhhn;
        float nval = tanh_approx(fmaf(taur, 0.5f * dnb, fmaf(0.5f, dnb, ain)));
        float dd   = h_old - nval;                          // h = n + z*(h-n)
        h_old = fmaf(tauz, 0.5f * dd, fmaf(0.5f, dd, nval));

        if (q == 0) h_sh[nxt][m][joff] = h_old;
        bar_group(barid);
        xv = xnext;
    }

    // ---- out[b] = h . W_fc + b_fc ----
    float v = (q == 0) ? h_old * wfc : 0.0f;
    #pragma unroll
    for (int o = 16; o > 0; o >>= 1)
        v += __shfl_xor_sync(0xffffffffu, v, o);
    if (lane == 0) red_sh[m][wg] = v;
    __syncthreads();
    if (u == 0 && b < Btotal) {
        float s = bfc;
        #pragma unroll
        for (int i = 0; i < 8; i++) s += red_sh[m][i];
        out[b] = s;
    }
}

extern "C" void kernel_launch(void* const* d_in, const int* in_sizes, int n_in,
                              void* d_out, int out_size)
{
    const float* x    = (const float*)d_in[0];
    const float* W_ih = (const float*)d_in[1];
    const float* W_hh = (const float*)d_in[2];
    const float* b_ih = (const float*)d_in[3];
    const float* b_hh = (const float*)d_in[4];
    const float* W_fc = (const float*)d_in[5];
    const float* b_fc = (const float*)d_in[6];

    int B = out_size;                 // 256
    int T = in_sizes[0] / B;          // 3000
    int grid = (B + 1) / 2;           // 128 CTAs -> 1 per SM

    gru_scan_kernel<<<grid, NTHREADS>>>(x, W_ih, W_hh, b_ih, b_hh, W_fc, b_fc,
                                        (float*)d_out, B, T);
}

// round 9
// speedup vs baseline: 1.2626x; 1.2626x over previous
#include <cuda_runtime.h>

#define HIDDEN   64
#define GROUP    128     // threads per batch element: (unit j, k-half)
#define NTHREADS 256     // 2 batch groups per CTA, 8 warps

// ---------- packed f32x2 helpers ----------
__device__ __forceinline__ unsigned long long ffma2(unsigned long long a,
                                                    unsigned long long b,
                                                    unsigned long long c) {
    unsigned long long d;
    asm("fma.rn.f32x2 %0, %1, %2, %3;" : "=l"(d) : "l"(a), "l"(b), "l"(c));
    return d;
}
__device__ __forceinline__ unsigned long long fadd2(unsigned long long a,
                                                    unsigned long long b) {
    unsigned long long d;
    asm("add.rn.f32x2 %0, %1, %2;" : "=l"(d) : "l"(a), "l"(b));
    return d;
}
__device__ __forceinline__ unsigned long long pack2(float lo, float hi) {
    unsigned long long r;
    asm("mov.b64 %0, {%1, %2};" : "=l"(r) : "f"(lo), "f"(hi));
    return r;
}
__device__ __forceinline__ float2 unpack2(unsigned long long v) {
    float2 r;
    asm("mov.b64 {%0, %1}, %2;" : "=f"(r.x), "=f"(r.y) : "l"(v));
    return r;
}
__device__ __forceinline__ float tanh_approx(float x) {   // 1 MUFU
    float r; asm("tanh.approx.f32 %0, %1;" : "=f"(r) : "f"(x)); return r;
}

// named barrier per 128-thread batch group
__device__ __forceinline__ void bar_group(int id) {
    asm volatile("bar.sync %0, %1;" :: "r"(id), "r"(GROUP) : "memory");
}

struct GruConsts {
    float wr_h, br_h, wz_h, bz_h, wn, bihn, bhhn;
};

// 16 packed FFMA2 over one gate half-row, 4 chains
__device__ __forceinline__ float half_dot(const unsigned long long* wg_,
                                          const unsigned long long* hv) {
    unsigned long long q0 = ffma2(wg_[0], hv[0], 0ull);
    unsigned long long q1 = ffma2(wg_[1], hv[1], 0ull);
    unsigned long long q2 = ffma2(wg_[2], hv[2], 0ull);
    unsigned long long q3 = ffma2(wg_[3], hv[3], 0ull);
    #pragma unroll
    for (int i = 1; i < 4; i++) {
        q0 = ffma2(wg_[4 * i],     hv[4 * i],     q0);
        q1 = ffma2(wg_[4 * i + 1], hv[4 * i + 1], q1);
        q2 = ffma2(wg_[4 * i + 2], hv[4 * i + 2], q2);
        q3 = ffma2(wg_[4 * i + 3], hv[4 * i + 3], q3);
    }
    float2 sp = unpack2(fadd2(fadd2(q0, q1), fadd2(q2, q3)));
    return sp.x + sp.y;
}

// one GRU timestep: reads hin (SMEM), updates h_old (reg), writes hout (SMEM)
__device__ __forceinline__ void gru_step(float xv,
                                         const float* __restrict__ hin,
                                         float* __restrict__ hout,
                                         const unsigned long long (*wreg)[16],
                                         const GruConsts& c,
                                         float& h_old,
                                         int half, int j, int barid)
{
    // x-terms (independent of h)
    float arh = fmaf(xv, c.wr_h, c.br_h);
    float azh = fmaf(xv, c.wz_h, c.bz_h);
    float ain = fmaf(xv, c.wn,   c.bihn);

    // load my k-half of h once (8 LDS.128), reuse for 3 gates
    unsigned long long hv[16];
    const ulonglong2* h2 = reinterpret_cast<const ulonglong2*>(hin + half * 32);
    #pragma unroll
    for (int i = 0; i < 8; i++) {
        ulonglong2 v = h2[i];
        hv[2 * i]     = v.x;
        hv[2 * i + 1] = v.y;
    }

    // ---- r gate first: its MUFU overlaps the n-dot issue ----
    float dr = half_dot(wreg[0], hv);
    dr += __shfl_xor_sync(0xffffffffu, dr, 16);
    float taur = tanh_approx(fmaf(0.5f, dr, arh));

    // ---- n gate second: nval MUFU overlaps the z-dot issue ----
    float dn = half_dot(wreg[2], hv);
    dn += __shfl_xor_sync(0xffffffffu, dn, 16);
    float dnb  = dn + c.bhhn;
    float nval = tanh_approx(fmaf(taur, 0.5f * dnb, fmaf(0.5f, dnb, ain)));

    // ---- z gate last ----
    float dz = half_dot(wreg[1], hv);
    dz += __shfl_xor_sync(0xffffffffu, dz, 16);
    float tauz = tanh_approx(fmaf(0.5f, dz, azh));

    float dd = h_old - nval;                       // h = n + z*(h-n)
    h_old = fmaf(tauz, 0.5f * dd, fmaf(0.5f, dd, nval));

    if (half == 0) hout[j] = h_old;
    bar_group(barid);
}

__global__ void __launch_bounds__(NTHREADS, 1)
gru_scan_kernel(const float* __restrict__ x,
                const float* __restrict__ W_ih,
                const float* __restrict__ W_hh,
                const float* __restrict__ b_ih,
                const float* __restrict__ b_hh,
                const float* __restrict__ W_fc,
                const float* __restrict__ b_fc,
                float* __restrict__ out,
                int Btotal, int T)
{
    __shared__ __align__(16) float h_sh[2][2][HIDDEN];   // [parity][group][j]
    __shared__ float red_sh[2][4];

    const int tid  = threadIdx.x;
    const int m    = tid / GROUP;            // batch group (warps 0-3 | 4-7)
    const int u    = tid % GROUP;
    const int wg   = u / 32;                 // warp within group 0..3
    const int lane = u % 32;
    const int j    = wg * 16 + (lane & 15);  // hidden unit
    const int half = lane >> 4;              // k-half; partner = lane^16
    const int b    = blockIdx.x * 2 + m;
    const int barid = 1 + m;

    // ---- all 3 gate half-rows in registers: 3 x 16 packed f32x2 ----
    unsigned long long wreg[3][16];
    #pragma unroll
    for (int g = 0; g < 3; g++) {
        const float4* row = reinterpret_cast<const float4*>(
            W_hh + (g * HIDDEN + j) * HIDDEN + half * 32);
        #pragma unroll
        for (int i = 0; i < 8; i++) {
            float4 v = row[i];
            wreg[g][2 * i]     = pack2(v.x, v.y);
            wreg[g][2 * i + 1] = pack2(v.z, v.w);
        }
    }

    GruConsts c;
    c.wr_h = 0.5f * W_ih[j];
    c.br_h = 0.5f * (b_ih[j] + b_hh[j]);
    c.wz_h = 0.5f * W_ih[HIDDEN + j];
    c.bz_h = 0.5f * (b_ih[HIDDEN + j] + b_hh[HIDDEN + j]);
    c.wn   = W_ih[2 * HIDDEN + j];
    c.bihn = b_ih[2 * HIDDEN + j];
    c.bhhn = b_hh[2 * HIDDEN + j];
    const float wfc = W_fc[j];
    const float bfc = __ldg(b_fc);

    const float* xb = x + (size_t)((b < Btotal) ? b : 0) * T;
    float h_old = 0.0f;
    if (half == 0) h_sh[0][m][j] = 0.0f;
    __syncthreads();

    // T is even (3000); unroll by 2 with statically-resolved ping-pong buffers
    float2 xq = *reinterpret_cast<const float2*>(xb);
    const int Teven = T & ~1;
    for (int t = 0; t < Teven; t += 2) {
        int tn = t + 2;
        if (tn > Teven - 2) tn = Teven - 2;
        float2 xq_next = *reinterpret_cast<const float2*>(xb + tn);

        gru_step(xq.x, h_sh[0][m], h_sh[1][m], wreg, c, h_old, half, j, barid);
        gru_step(xq.y, h_sh[1][m], h_sh[0][m], wreg, c, h_old, half, j, barid);

        xq = xq_next;
    }
    if (Teven != T) {   // odd tail (not hit for T=3000)
        float xv = __ldg(xb + Teven);
        gru_step(xv, h_sh[0][m], h_sh[1][m], wreg, c, h_old, half, j, barid);
    }

    // ---- out[b] = h . W_fc + b_fc (h identical in both halves' regs) ----
    float v = (half == 0) ? h_old * wfc : 0.0f;
    #pragma unroll
    for (int o = 16; o > 0; o >>= 1)
        v += __shfl_xor_sync(0xffffffffu, v, o);
    if (lane == 0) red_sh[m][wg] = v;
    __syncthreads();
    if (u == 0 && b < Btotal) {
        out[b] = red_sh[m][0] + red_sh[m][1] + red_sh[m][2] + red_sh[m][3] + bfc;
    }
}

extern "C" void kernel_launch(void* const* d_in, const int* in_sizes, int n_in,
                              void* d_out, int out_size)
{
    const float* x    = (const float*)d_in[0];
    const float* W_ih = (const float*)d_in[1];
    const float* W_hh = (const float*)d_in[2];
    const float* b_ih = (const float*)d_in[3];
    const float* b_hh = (const float*)d_in[4];
    const float* W_fc = (const float*)d_in[5];
    const float* b_fc = (const float*)d_in[6];

    int B = out_size;                 // 256
    int T = in_sizes[0] / B;          // 3000
    int grid = (B + 1) / 2;           // 128 CTAs -> 1 per SM

    gru_scan_kernel<<<grid, NTHREADS>>>(x, W_ih, W_hh, b_ih, b_hh, W_fc, b_fc,
                                        (float*)d_out, B, T);
}

// round 10
// speedup vs baseline: 1.3244x; 1.0489x over previous
#include <cuda_runtime.h>

#define HIDDEN   64
#define NTHREADS 128     // one batch element per CTA; thread = (unit j, k-half)

// ---------- packed f32x2 helpers ----------
__device__ __forceinline__ unsigned long long ffma2(unsigned long long a,
                                                    unsigned long long b,
                                                    unsigned long long c) {
    unsigned long long d;
    asm("fma.rn.f32x2 %0, %1, %2, %3;" : "=l"(d) : "l"(a), "l"(b), "l"(c));
    return d;
}
__device__ __forceinline__ unsigned long long fadd2(unsigned long long a,
                                                    unsigned long long b) {
    unsigned long long d;
    asm("add.rn.f32x2 %0, %1, %2;" : "=l"(d) : "l"(a), "l"(b));
    return d;
}
__device__ __forceinline__ unsigned long long pack2(float lo, float hi) {
    unsigned long long r;
    asm("mov.b64 %0, {%1, %2};" : "=l"(r) : "f"(lo), "f"(hi));
    return r;
}
__device__ __forceinline__ float2 unpack2(unsigned long long v) {
    float2 r;
    asm("mov.b64 {%0, %1}, %2;" : "=f"(r.x), "=f"(r.y) : "l"(v));
    return r;
}
__device__ __forceinline__ float tanh_approx(float x) {   // 1 MUFU
    float r; asm("tanh.approx.f32 %0, %1;" : "=f"(r) : "f"(x)); return r;
}

struct GruConsts {
    float wr_h, br_h, wz_h, bz_h, wn, bihn, bhhn;
};

// 16 packed FFMA2 over one gate half-row, 4 chains
__device__ __forceinline__ float half_dot(const unsigned long long* wg_,
                                          const unsigned long long* hv) {
    unsigned long long q0 = ffma2(wg_[0], hv[0], 0ull);
    unsigned long long q1 = ffma2(wg_[1], hv[1], 0ull);
    unsigned long long q2 = ffma2(wg_[2], hv[2], 0ull);
    unsigned long long q3 = ffma2(wg_[3], hv[3], 0ull);
    #pragma unroll
    for (int i = 1; i < 4; i++) {
        q0 = ffma2(wg_[4 * i],     hv[4 * i],     q0);
        q1 = ffma2(wg_[4 * i + 1], hv[4 * i + 1], q1);
        q2 = ffma2(wg_[4 * i + 2], hv[4 * i + 2], q2);
        q3 = ffma2(wg_[4 * i + 3], hv[4 * i + 3], q3);
    }
    float2 sp = unpack2(fadd2(fadd2(q0, q1), fadd2(q2, q3)));
    return sp.x + sp.y;
}

// one GRU timestep: reads hin (SMEM), updates h_old (reg), writes hout (SMEM)
// plain __syncthreads (BAR0, ~7cyc floor) instead of named barrier (~47cyc)
__device__ __forceinline__ void gru_step(float xv,
                                         const float* __restrict__ hin,
                                         float* __restrict__ hout,
                                         const unsigned long long (*wreg)[16],
                                         const GruConsts& c,
                                         float& h_old,
                                         int half, int j)
{
    // x-terms (independent of h)
    float arh = fmaf(xv, c.wr_h, c.br_h);
    float azh = fmaf(xv, c.wz_h, c.bz_h);
    float ain = fmaf(xv, c.wn,   c.bihn);

    // load my k-half of h once (8 LDS.128 broadcast), reuse for 3 gates
    unsigned long long hv[16];
    const ulonglong2* h2 = reinterpret_cast<const ulonglong2*>(hin + half * 32);
    #pragma unroll
    for (int i = 0; i < 8; i++) {
        ulonglong2 v = h2[i];
        hv[2 * i]     = v.x;
        hv[2 * i + 1] = v.y;
    }

    // ---- r gate first: its MUFU overlaps the n-dot issue ----
    float dr = half_dot(wreg[0], hv);
    dr += __shfl_xor_sync(0xffffffffu, dr, 16);
    float taur = tanh_approx(fmaf(0.5f, dr, arh));

    // ---- n gate second: nval MUFU overlaps the z-dot issue ----
    float dn = half_dot(wreg[2], hv);
    dn += __shfl_xor_sync(0xffffffffu, dn, 16);
    float dnb  = dn + c.bhhn;
    float nval = tanh_approx(fmaf(taur, 0.5f * dnb, fmaf(0.5f, dnb, ain)));

    // ---- z gate last ----
    float dz = half_dot(wreg[1], hv);
    dz += __shfl_xor_sync(0xffffffffu, dz, 16);
    float tauz = tanh_approx(fmaf(0.5f, dz, azh));

    float dd = h_old - nval;                       // h = n + z*(h-n)
    h_old = fmaf(tauz, 0.5f * dd, fmaf(0.5f, dd, nval));

    if (half == 0) hout[j] = h_old;
    __syncthreads();
}

__global__ void __launch_bounds__(NTHREADS, 2)
gru_scan_kernel(const float* __restrict__ x,
                const float* __restrict__ W_ih,
                const float* __restrict__ W_hh,
                const float* __restrict__ b_ih,
                const float* __restrict__ b_hh,
                const float* __restrict__ W_fc,
                const float* __restrict__ b_fc,
                float* __restrict__ out,
                int Btotal, int T)
{
    __shared__ __align__(16) float h_sh[2][HIDDEN];   // ping-pong by parity
    __shared__ float red_sh[4];

    const int tid  = threadIdx.x;
    const int wg   = tid / 32;                 // warp 0..3
    const int lane = tid % 32;
    const int j    = wg * 16 + (lane & 15);    // hidden unit
    const int half = lane >> 4;                // k-half; partner = lane^16
    const int b    = blockIdx.x;               // one batch per CTA

    // ---- all 3 gate half-rows in registers: 3 x 16 packed f32x2 ----
    unsigned long long wreg[3][16];
    #pragma unroll
    for (int g = 0; g < 3; g++) {
        const float4* row = reinterpret_cast<const float4*>(
            W_hh + (g * HIDDEN + j) * HIDDEN + half * 32);
        #pragma unroll
        for (int i = 0; i < 8; i++) {
            float4 v = row[i];
            wreg[g][2 * i]     = pack2(v.x, v.y);
            wreg[g][2 * i + 1] = pack2(v.z, v.w);
        }
    }

    GruConsts c;
    c.wr_h = 0.5f * W_ih[j];
    c.br_h = 0.5f * (b_ih[j] + b_hh[j]);
    c.wz_h = 0.5f * W_ih[HIDDEN + j];
    c.bz_h = 0.5f * (b_ih[HIDDEN + j] + b_hh[HIDDEN + j]);
    c.wn   = W_ih[2 * HIDDEN + j];
    c.bihn = b_ih[2 * HIDDEN + j];
    c.bhhn = b_hh[2 * HIDDEN + j];
    const float wfc = W_fc[j];
    const float bfc = __ldg(b_fc);

    const float* xb = x + (size_t)b * T;
    float h_old = 0.0f;
    if (half == 0) h_sh[0][j] = 0.0f;
    __syncthreads();

    // T is even (3000); unroll by 2 with statically-resolved ping-pong buffers
    float2 xq = *reinterpret_cast<const float2*>(xb);
    const int Teven = T & ~1;
    for (int t = 0; t < Teven; t += 2) {
        int tn = t + 2;
        if (tn > Teven - 2) tn = Teven - 2;
        float2 xq_next = *reinterpret_cast<const float2*>(xb + tn);

        gru_step(xq.x, h_sh[0], h_sh[1], wreg, c, h_old, half, j);
        gru_step(xq.y, h_sh[1], h_sh[0], wreg, c, h_old, half, j);

        xq = xq_next;
    }
    if (Teven != T) {   // odd tail (not hit for T=3000)
        float xv = __ldg(xb + Teven);
        gru_step(xv, h_sh[0], h_sh[1], wreg, c, h_old, half, j);
    }

    // ---- out[b] = h . W_fc + b_fc (h identical in both halves' regs) ----
    float v = (half == 0) ? h_old * wfc : 0.0f;
    #pragma unroll
    for (int o = 16; o > 0; o >>= 1)
        v += __shfl_xor_sync(0xffffffffu, v, o);
    if (lane == 0) red_sh[wg] = v;
    __syncthreads();
    if (tid == 0) {
        out[b] = red_sh[0] + red_sh[1] + red_sh[2] + red_sh[3] + bfc;
    }
}

extern "C" void kernel_launch(void* const* d_in, const int* in_sizes, int n_in,
                              void* d_out, int out_size)
{
    const float* x    = (const float*)d_in[0];
    const float* W_ih = (const float*)d_in[1];
    const float* W_hh = (const float*)d_in[2];
    const float* b_ih = (const float*)d_in[3];
    const float* b_hh = (const float*)d_in[4];
    const float* W_fc = (const float*)d_in[5];
    const float* b_fc = (const float*)d_in[6];

    int B = out_size;                 // 256
    int T = in_sizes[0] / B;          // 3000

    gru_scan_kernel<<<B, NTHREADS>>>(x, W_ih, W_hh, b_ih, b_hh, W_fc, b_fc,
                                     (float*)d_out, B, T);
}